// round 13
// baseline (speedup 1.0000x reference)
#include <cuda_runtime.h>
#include <cuda_fp16.h>
#include <math.h>
#include <stdint.h>

#define Gg 8
#define Ee 8
#define Ss 1024
#define Cc 256
#define Mdim 1024
#define Hh 5464
#define Hp 5504
#define Ntok (Gg*Ss)
#define GCv (Gg*Cc)

// ---------------- device scratch (fp16 operands) ----------------
__device__ __align__(256) __half g_a  [(size_t)Ee*GCv*Mdim];
__device__ __align__(256) __half g_w0t[(size_t)Ee*Hp*Mdim];
__device__ __align__(256) __half g_w1t[(size_t)Ee*Hp*Mdim];
__device__ __align__(256) __half g_wot[(size_t)Ee*Mdim*Hp];
__device__ __align__(256) __half g_hid[(size_t)Ee*GCv*Hp];
__device__ __align__(256) float g_expout[(size_t)Ee*GCv*Mdim];
__device__ int   g_idx1[Ntok];
__device__ int   g_idx2[Ntok];
__device__ float g_gate1[Ntok];
__device__ float g_gate2[Ntok];
__device__ int   g_slotsrc[Ee*GCv];
__device__ int2  g_tokinfo[Ntok];

// ---------------- helpers ----------------
__device__ __forceinline__ uint32_t s2u(const void* p){
    uint32_t a; asm("{ .reg .u64 t; cvta.to.shared.u64 t, %1; cvt.u32.u64 %0, t; }":"=r"(a):"l"(p)); return a;
}
__device__ __forceinline__ void cpa16(uint32_t d, const void* s){
    asm volatile("cp.async.cg.shared.global [%0], [%1], 16;"::"r"(d),"l"(s));
}
#define CP_COMMIT() asm volatile("cp.async.commit_group;":::"memory")
#define CP_WAIT2()  asm volatile("cp.async.wait_group 2;":::"memory")
#define CP_WAIT1()  asm volatile("cp.async.wait_group 1;":::"memory")
#define CP_WAIT0()  asm volatile("cp.async.wait_group 0;":::"memory")

#define LDSM4(R, addr) \
    asm volatile("ldmatrix.sync.aligned.m8n8.x4.shared.b16 {%0,%1,%2,%3}, [%4];" \
        : "=r"((R)[0]),"=r"((R)[1]),"=r"((R)[2]),"=r"((R)[3]) : "r"(addr))
#define MMA_F16(D, A, B) \
    asm volatile("mma.sync.aligned.m16n8k16.row.col.f32.f16.f16.f32 " \
        "{%0,%1,%2,%3}, {%4,%5,%6,%7}, {%8,%9}, {%0,%1,%2,%3};" \
        : "+f"((D)[0]),"+f"((D)[1]),"+f"((D)[2]),"+f"((D)[3]) \
        : "r"((A)[0]),"r"((A)[1]),"r"((A)[2]),"r"((A)[3]), "r"((B)[0]),"r"((B)[1]))

__device__ __forceinline__ uint32_t packh(float a, float b){
    __half2 h = __floats2half2_rn(a, b);
    return *(uint32_t*)&h;
}
__device__ __forceinline__ float gelu_f(float x){
    float u = 0.7978845608028654f*(x + 0.044715f*x*x*x);
    return 0.5f*x*(1.f + tanhf(u));
}

// ---------- router ----------
__global__ void k_router(const float* __restrict__ x, const float* __restrict__ rw){
    int t = (blockIdx.x*blockDim.x + threadIdx.x) >> 5;
    int lane = threadIdx.x & 31;
    if (t >= Ntok) return;
    const float* xr = x + (size_t)t*Mdim;
    float acc[Ee];
#pragma unroll
    for (int e = 0; e < Ee; e++) acc[e] = 0.f;
    for (int m = lane; m < Mdim; m += 32){
        float xv = xr[m];
        const float4* r4 = (const float4*)(rw + m*Ee);
        float4 rA = r4[0], rB = r4[1];
        acc[0]=fmaf(xv,rA.x,acc[0]); acc[1]=fmaf(xv,rA.y,acc[1]);
        acc[2]=fmaf(xv,rA.z,acc[2]); acc[3]=fmaf(xv,rA.w,acc[3]);
        acc[4]=fmaf(xv,rB.x,acc[4]); acc[5]=fmaf(xv,rB.y,acc[5]);
        acc[6]=fmaf(xv,rB.z,acc[6]); acc[7]=fmaf(xv,rB.w,acc[7]);
    }
#pragma unroll
    for (int e = 0; e < Ee; e++)
#pragma unroll
        for (int o = 16; o > 0; o >>= 1)
            acc[e] += __shfl_xor_sync(0xffffffffu, acc[e], o);
    if (lane == 0){
        float mx = acc[0];
#pragma unroll
        for (int e = 1; e < Ee; e++) mx = fmaxf(mx, acc[e]);
        float p[Ee]; float sum = 0.f;
#pragma unroll
        for (int e = 0; e < Ee; e++){ p[e] = expf(acc[e]-mx); sum += p[e]; }
        float inv = 1.f/sum;
#pragma unroll
        for (int e = 0; e < Ee; e++) p[e] *= inv;
        int i1 = 0; float b1 = p[0];
#pragma unroll
        for (int e = 1; e < Ee; e++) if (p[e] > b1){ b1 = p[e]; i1 = e; }
        int i2 = -1; float b2 = -1.f;
#pragma unroll
        for (int e = 0; e < Ee; e++) if (e != i1 && p[e] > b2){ b2 = p[e]; i2 = e; }
        g_idx1[t]=i1; g_idx2[t]=i2; g_gate1[t]=b1; g_gate2[t]=b2;
    }
}

// ---------- capacity ----------
__global__ void k_capacity(){
    int g = blockIdx.x, tid = threadIdx.x;
    __shared__ int s_i1[Ss], s_i2[Ss], s_p1[Ss], s_p2[Ss];
    __shared__ int s_slot[Ee*Cc];
    __shared__ int s_cnt[Ee], s_m1c[Ee];
    for (int s = tid; s < Ss; s += blockDim.x){
        s_i1[s] = g_idx1[g*Ss+s]; s_i2[s] = g_idx2[g*Ss+s];
    }
    for (int i = tid; i < Ee*Cc; i += blockDim.x) s_slot[i] = -1;
    if (tid < Ee) s_cnt[tid] = 0;
    __syncthreads();
    if (tid == 0){
        for (int s = 0; s < Ss; s++){
            int e = s_i1[s]; int p = s_cnt[e]++;
            if (p < Cc){ s_p1[s] = p; s_slot[e*Cc+p] = s; } else s_p1[s] = -1;
        }
#pragma unroll
        for (int e = 0; e < Ee; e++){ s_m1c[e] = min(s_cnt[e], Cc); s_cnt[e] = 0; }
        for (int s = 0; s < Ss; s++){
            int e = s_i2[s]; int p = s_cnt[e]++ + s_m1c[e];
            if (p < Cc){ s_p2[s] = p; s_slot[e*Cc+p] = s; } else s_p2[s] = -1;
        }
    }
    __syncthreads();
    for (int i = tid; i < Ee*Cc; i += blockDim.x){
        int e = i/Cc, c = i%Cc;
        g_slotsrc[e*GCv + g*Cc + c] = s_slot[i];
    }
    for (int s = tid; s < Ss; s += blockDim.x){
        int p1 = s_p1[s], p2 = s_p2[s], e1 = s_i1[s], e2 = s_i2[s];
        g_tokinfo[g*Ss+s] = make_int2(p1 >= 0 ? e1*GCv + g*Cc + p1 : -1,
                                      p2 >= 0 ? e2*GCv + g*Cc + p2 : -1);
    }
}

// ---------- transpose+convert body ----------
__device__ __forceinline__ void splitT_body(const float* __restrict__ src,
                                            __half* __restrict__ dst,
                                            int e, int r0, int c0,
                                            int R, int C, int Cp, int Rp, int tid){
    __shared__ float t[32][33];
    int tx = tid & 31, ty = tid >> 5;
    const float* s = src + (size_t)e*R*C;
#pragma unroll
    for (int i = 0; i < 4; i++){
        int rr = r0+ty+i*8, cc = c0+tx;
        t[ty+i*8][tx] = (rr < R && cc < C) ? s[(size_t)rr*C+cc] : 0.f;
    }
    __syncthreads();
    size_t dbase = (size_t)e*Cp*Rp;
#pragma unroll
    for (int i = 0; i < 4; i++){
        int dr = c0+ty+i*8, dc = r0+tx;
        if (dr < Cp && dc < Rp)
            dst[dbase + (size_t)dr*Rp + dc] = __float2half_rn(t[tx][ty+i*8]);
    }
}

// ---------- fused prep ----------
#define NGATH (Ee*GCv)                          // 16384
#define NSPL  (32*172*Ee)                        // 44032
#define NSPLW (172*32*Ee)                        // 44032
__global__ void k_prep(const float* __restrict__ x,
                       const float* __restrict__ w0,
                       const float* __restrict__ w1,
                       const float* __restrict__ wo){
    int b = blockIdx.x;
    int tid = threadIdx.x;
    if (b < NGATH){
        int row = b;
        int g = (row % GCv) / Cc;
        int src = g_slotsrc[row];
        float4 v = make_float4(0.f,0.f,0.f,0.f);
        if (src >= 0) v = ((const float4*)(x + (size_t)(g*Ss+src)*Mdim))[tid];
        ((uint2*)(g_a + (size_t)row*Mdim))[tid] = make_uint2(packh(v.x,v.y), packh(v.z,v.w));
        return;
    }
    int b2 = b - NGATH;
    if (b2 < 2*NSPL){
        int which = b2 / NSPL;
        int r = b2 % NSPL;
        int bx = r % 32;
        int by = (r / 32) % 172;
        int e  = r / (32*172);
        splitT_body(which ? w1 : w0, which ? g_w1t : g_w0t,
                    e, bx*32, by*32, Mdim, Hh, Hp, Mdim, tid);
    } else {
        int r = b2 - 2*NSPL;
        int bx = r % 172;
        int by = (r / 172) % 32;
        int e  = r / (172*32);
        splitT_body(wo, g_wot, e, bx*32, by*32, Hh, Mdim, Mdim, Hp, tid);
    }
}

#define ROWB  144                    // 64 halfs (128B) + 16B pad
#define MATB  18432                  // 128 rows x 144B

// ---------- fused GEMM1 (fp16): A x {W0,W1} -> gelu*mul -> hid fp16 ----------
// 512 threads, CTA 128x128, warps 4x4 (warp 32x32), K-step 64, 4-stage pipeline.
#define STG1 (3*MATB)                // A, B0, B1 = 55296/stage
__global__ void __launch_bounds__(512, 1) k_mma1(){
    constexpr int K = Mdim;
    constexpr int NKS = K / 64;      // 16

    extern __shared__ __align__(128) char smem[];
    const uint32_t sb = s2u(smem);

    const int tid  = threadIdx.x;
    const int lane = tid & 31;
    const int wrp  = tid >> 5;
    const int wm   = (wrp >> 2) * 32;
    const int wn   = (wrp & 3) * 32;
    const int e  = blockIdx.z;
    const int bm = blockIdx.y * 128;
    const int bn = blockIdx.x * 128;

    const char* pA  = (const char*)(g_a   + ((size_t)e*GCv + bm)*K);
    const char* pB0 = (const char*)(g_w0t + ((size_t)e*Hp  + bn)*K);
    const char* pB1 = (const char*)(g_w1t + ((size_t)e*Hp  + bn)*K);

    auto load_stage = [&](int ks, int buf){
        uint32_t s = sb + buf*STG1;
        size_t ko = (size_t)ks * 128;            // 64 halfs = 128 bytes
#pragma unroll
        for (int it = 0; it < 2; it++){
            int ci = tid*2 + it;                 // 1024 chunks per matrix
            int r = ci >> 3, q = (ci & 7)*16;
            uint32_t so = (uint32_t)(r*ROWB + q);
            size_t go = (size_t)r*(K*2) + ko + q;
            cpa16(s +          so, pA  + go);
            cpa16(s + MATB   + so, pB0 + go);
            cpa16(s + 2*MATB + so, pB1 + go);
        }
        CP_COMMIT();
    };

    float d0[2][4][4], d1[2][4][4];
#pragma unroll
    for (int i = 0; i < 2; i++)
#pragma unroll
        for (int j = 0; j < 4; j++)
#pragma unroll
            for (int q = 0; q < 4; q++){ d0[i][j][q] = 0.f; d1[i][j][q] = 0.f; }

    load_stage(0, 0);
    load_stage(1, 1);
    load_stage(2, 2);

    const uint32_t brow = (uint32_t)((lane & 7) + ((lane >> 4) & 1)*8);
    const uint32_t bcol = (uint32_t)(((lane >> 3) & 1)*16);
    const uint32_t arow = (uint32_t)(lane & 15);
    const uint32_t acol = (uint32_t)((lane >> 4)*16);

    for (int ks = 0; ks < NKS; ks++){
        if (ks < NKS-2)       CP_WAIT2();
        else if (ks == NKS-2) CP_WAIT1();
        else                  CP_WAIT0();
        __syncthreads();
        if (ks + 3 < NKS) load_stage(ks + 3, (ks + 3) & 3);

        uint32_t s0 = sb + (ks & 3)*STG1;
#pragma unroll
        for (int kk = 0; kk < 4; kk++){
            uint32_t a[2][4], b0[2][4], b1[2][4];
#pragma unroll
            for (int mt = 0; mt < 2; mt++){
                uint32_t ad = s0 + (uint32_t)(wm + mt*16)*ROWB + arow*ROWB
                                 + (uint32_t)kk*32 + acol;
                LDSM4(a[mt], ad);
            }
#pragma unroll
            for (int np = 0; np < 2; np++){
                uint32_t bd = s0 + MATB + (uint32_t)(wn + np*16)*ROWB + brow*ROWB
                                 + (uint32_t)kk*32 + bcol;
                LDSM4(b0[np], bd);
                LDSM4(b1[np], bd + MATB);
            }
#pragma unroll
            for (int mt = 0; mt < 2; mt++)
#pragma unroll
                for (int np = 0; np < 2; np++){
                    MMA_F16(d0[mt][np*2+0], a[mt], (&b0[np][0]));
                    MMA_F16(d0[mt][np*2+1], a[mt], (&b0[np][2]));
                    MMA_F16(d1[mt][np*2+0], a[mt], (&b1[np][0]));
                    MMA_F16(d1[mt][np*2+1], a[mt], (&b1[np][2]));
                }
        }
    }

    const int rb = bm + wm + (lane >> 2);
    const int cb = bn + wn + 2*(lane & 3);
#pragma unroll
    for (int mt = 0; mt < 2; mt++)
#pragma unroll
        for (int nt = 0; nt < 4; nt++)
#pragma unroll
            for (int h = 0; h < 2; h++){
                int row = rb + mt*16 + h*8;
                int col = cb + nt*8;
                float ha = gelu_f(d0[mt][nt][h*2+0]) * d1[mt][nt][h*2+0];
                float hb = gelu_f(d0[mt][nt][h*2+1]) * d1[mt][nt][h*2+1];
                size_t idx = ((size_t)e*GCv + row)*(size_t)Hp + col;
                *(uint32_t*)(g_hid + idx) = packh(ha, hb);
            }
}

// ---------- GEMM2 (fp16): hid x woT -> expout fp32 ----------
// 4-stage pipeline + register double-buffered fragments.
#define STG2 (2*MATB)                // A, B = 36864/stage
__global__ void __launch_bounds__(512, 1) k_mma2(){
    constexpr int K = Hp;
    constexpr int NKS = K / 64;      // 86

    extern __shared__ __align__(128) char smem[];
    const uint32_t sb = s2u(smem);

    const int tid  = threadIdx.x;
    const int lane = tid & 31;
    const int wrp  = tid >> 5;
    const int wm   = (wrp >> 2) * 32;
    const int wn   = (wrp & 3) * 32;
    const int e  = blockIdx.z;
    const int bm = blockIdx.y * 128;
    const int bn = blockIdx.x * 128;

    const char* pA = (const char*)(g_hid + ((size_t)e*GCv  + bm)*K);
    const char* pB = (const char*)(g_wot + ((size_t)e*Mdim + bn)*K);

    auto load_stage = [&](int ks, int buf){
        uint32_t s = sb + buf*STG2;
        size_t ko = (size_t)ks * 128;
#pragma unroll
        for (int it = 0; it < 2; it++){
            int ci = tid*2 + it;
            int r = ci >> 3, q = (ci & 7)*16;
            uint32_t so = (uint32_t)(r*ROWB + q);
            size_t go = (size_t)r*(K*2) + ko + q;
            cpa16(s +        so, pA + go);
            cpa16(s + MATB + so, pB + go);
        }
        CP_COMMIT();
    };

    float d[2][4][4];
#pragma unroll
    for (int i = 0; i < 2; i++)
#pragma unroll
        for (int j = 0; j < 4; j++)
#pragma unroll
            for (int q = 0; q < 4; q++) d[i][j][q] = 0.f;

    load_stage(0, 0);
    load_stage(1, 1);
    load_stage(2, 2);

    const uint32_t brow = (uint32_t)((lane & 7) + ((lane >> 4) & 1)*8);
    const uint32_t bcol = (uint32_t)(((lane >> 3) & 1)*16);
    const uint32_t arow = (uint32_t)(lane & 15);
    const uint32_t acol = (uint32_t)((lane >> 4)*16);

    uint32_t a[2][2][4], b[2][2][4];     // [buf][mt/np][4]

    auto load_frags = [&](uint32_t s0, int kk, int fb){
#pragma unroll
        for (int mt = 0; mt < 2; mt++){
            uint32_t ad = s0 + (uint32_t)(wm + mt*16)*ROWB + arow*ROWB
                             + (uint32_t)kk*32 + acol;
            LDSM4(a[fb][mt], ad);
        }
#pragma unroll
        for (int np = 0; np < 2; np++){
            uint32_t bd = s0 + MATB + (uint32_t)(wn + np*16)*ROWB + brow*ROWB
                             + (uint32_t)kk*32 + bcol;
            LDSM4(b[fb][np], bd);
        }
    };

    for (int ks = 0; ks < NKS; ks++){
        if (ks < NKS-2)       CP_WAIT2();
        else if (ks == NKS-2) CP_WAIT1();
        else                  CP_WAIT0();
        __syncthreads();
        if (ks + 3 < NKS) load_stage(ks + 3, (ks + 3) & 3);

        uint32_t s0 = sb + (ks & 3)*STG2;
        load_frags(s0, 0, 0);
#pragma unroll
        for (int kk = 0; kk < 4; kk++){
            int cur = kk & 1;
            if (kk < 3) load_frags(s0, kk + 1, cur ^ 1);
#pragma unroll
            for (int mt = 0; mt < 2; mt++)
#pragma unroll
                for (int np = 0; np < 2; np++){
                    MMA_F16(d[mt][np*2+0], a[cur][mt], (&b[cur][np][0]));
                    MMA_F16(d[mt][np*2+1], a[cur][mt], (&b[cur][np][2]));
                }
        }
    }

    const int rb = bm + wm + (lane >> 2);
    const int cb = bn + wn + 2*(lane & 3);
#pragma unroll
    for (int mt = 0; mt < 2; mt++)
#pragma unroll
        for (int nt = 0; nt < 4; nt++)
#pragma unroll
            for (int h = 0; h < 2; h++){
                int row = rb + mt*16 + h*8;
                int col = cb + nt*8;
                size_t idx = ((size_t)e*GCv + row)*(size_t)Mdim + col;
                *(float2*)(g_expout + idx) = make_float2(d[mt][nt][h*2+0], d[mt][nt][h*2+1]);
            }
}

// ---------- combine ----------
__global__ void k_combine(float* __restrict__ out){
    int t = blockIdx.x, i = threadIdx.x;
    int2 info = g_tokinfo[t];
    float4 acc = make_float4(0.f,0.f,0.f,0.f);
    if (info.x >= 0){
        float gv = g_gate1[t];
        float4 v = ((const float4*)(g_expout + (size_t)info.x*Mdim))[i];
        acc.x += gv*v.x; acc.y += gv*v.y; acc.z += gv*v.z; acc.w += gv*v.w;
    }
    if (info.y >= 0){
        float gv = g_gate2[t];
        float4 v = ((const float4*)(g_expout + (size_t)info.y*Mdim))[i];
        acc.x += gv*v.x; acc.y += gv*v.y; acc.z += gv*v.z; acc.w += gv*v.w;
    }
    ((float4*)(out + (size_t)t*Mdim))[i] = acc;
}

// ---------- launch ----------
extern "C" void kernel_launch(void* const* d_in, const int* in_sizes, int n_in,
                              void* d_out, int out_size){
    const float* x  = (const float*)d_in[0];
    const float* rw = (const float*)d_in[1];
    const float* w0 = (const float*)d_in[2];
    const float* w1 = (const float*)d_in[3];
    const float* wo = (const float*)d_in[4];
    float* out = (float*)d_out;

    static bool attr_done = false;
    if (!attr_done){
        cudaFuncSetAttribute(k_mma1, cudaFuncAttributeMaxDynamicSharedMemorySize, 4*STG1);
        cudaFuncSetAttribute(k_mma2, cudaFuncAttributeMaxDynamicSharedMemorySize, 4*STG2);
        attr_done = true;
    }

    // k_mma1 is the 4th launch (the one ncu captures)
    k_router<<<Ntok/8, 256>>>(x, rw);                                    // 1
    k_capacity<<<Gg, 256>>>();                                           // 2
    k_prep<<<NGATH + 2*NSPL + NSPLW, 256>>>(x, w0, w1, wo);              // 3
    k_mma1<<<dim3(Hp/128,  GCv/128, Ee), 512, 4*STG1>>>();               // 4 <- profiled
    k_mma2<<<dim3(Mdim/128, GCv/128, Ee), 512, 4*STG2>>>();              // 5
    k_combine<<<Ntok, 256>>>(out);                                       // 6
}

// round 14
// speedup vs baseline: 1.0307x; 1.0307x over previous
#include <cuda_runtime.h>
#include <cuda_fp16.h>
#include <math.h>
#include <stdint.h>

#define Gg 8
#define Ee 8
#define Ss 1024
#define Cc 256
#define Mdim 1024
#define Hh 5464
#define Hp 5504
#define Ntok (Gg*Ss)
#define GCv (Gg*Cc)

// ---------------- device scratch (fp16 operands) ----------------
__device__ __align__(256) __half g_a  [(size_t)Ee*GCv*Mdim];
__device__ __align__(256) __half g_w0t[(size_t)Ee*Hp*Mdim];
__device__ __align__(256) __half g_w1t[(size_t)Ee*Hp*Mdim];
__device__ __align__(256) __half g_wot[(size_t)Ee*Mdim*Hp];
__device__ __align__(256) __half g_hid[(size_t)Ee*GCv*Hp];
__device__ __align__(256) float g_expout[(size_t)Ee*GCv*Mdim];
__device__ int   g_idx1[Ntok];
__device__ int   g_idx2[Ntok];
__device__ float g_gate1[Ntok];
__device__ float g_gate2[Ntok];
__device__ int   g_slotsrc[Ee*GCv];
__device__ int2  g_tokinfo[Ntok];

// ---------------- helpers ----------------
__device__ __forceinline__ uint32_t s2u(const void* p){
    uint32_t a; asm("{ .reg .u64 t; cvta.to.shared.u64 t, %1; cvt.u32.u64 %0, t; }":"=r"(a):"l"(p)); return a;
}
__device__ __forceinline__ void cpa16(uint32_t d, const void* s){
    asm volatile("cp.async.cg.shared.global [%0], [%1], 16;"::"r"(d),"l"(s));
}
#define CP_COMMIT() asm volatile("cp.async.commit_group;":::"memory")
#define CP_WAIT1()  asm volatile("cp.async.wait_group 1;":::"memory")
#define CP_WAIT0()  asm volatile("cp.async.wait_group 0;":::"memory")

#define LDSM4(R, addr) \
    asm volatile("ldmatrix.sync.aligned.m8n8.x4.shared.b16 {%0,%1,%2,%3}, [%4];" \
        : "=r"((R)[0]),"=r"((R)[1]),"=r"((R)[2]),"=r"((R)[3]) : "r"(addr))
#define MMA_F16(D, A, B) \
    asm volatile("mma.sync.aligned.m16n8k16.row.col.f32.f16.f16.f32 " \
        "{%0,%1,%2,%3}, {%4,%5,%6,%7}, {%8,%9}, {%0,%1,%2,%3};" \
        : "+f"((D)[0]),"+f"((D)[1]),"+f"((D)[2]),"+f"((D)[3]) \
        : "r"((A)[0]),"r"((A)[1]),"r"((A)[2]),"r"((A)[3]), "r"((B)[0]),"r"((B)[1]))

__device__ __forceinline__ uint32_t packh(float a, float b){
    __half2 h = __floats2half2_rn(a, b);
    return *(uint32_t*)&h;
}
__device__ __forceinline__ float gelu_f(float x){
    float u = 0.7978845608028654f*(x + 0.044715f*x*x*x);
    return 0.5f*x*(1.f + tanhf(u));
}

// ---------- router ----------
__global__ void k_router(const float* __restrict__ x, const float* __restrict__ rw){
    int t = (blockIdx.x*blockDim.x + threadIdx.x) >> 5;
    int lane = threadIdx.x & 31;
    if (t >= Ntok) return;
    const float* xr = x + (size_t)t*Mdim;
    float acc[Ee];
#pragma unroll
    for (int e = 0; e < Ee; e++) acc[e] = 0.f;
    for (int m = lane; m < Mdim; m += 32){
        float xv = xr[m];
        const float4* r4 = (const float4*)(rw + m*Ee);
        float4 rA = r4[0], rB = r4[1];
        acc[0]=fmaf(xv,rA.x,acc[0]); acc[1]=fmaf(xv,rA.y,acc[1]);
        acc[2]=fmaf(xv,rA.z,acc[2]); acc[3]=fmaf(xv,rA.w,acc[3]);
        acc[4]=fmaf(xv,rB.x,acc[4]); acc[5]=fmaf(xv,rB.y,acc[5]);
        acc[6]=fmaf(xv,rB.z,acc[6]); acc[7]=fmaf(xv,rB.w,acc[7]);
    }
#pragma unroll
    for (int e = 0; e < Ee; e++)
#pragma unroll
        for (int o = 16; o > 0; o >>= 1)
            acc[e] += __shfl_xor_sync(0xffffffffu, acc[e], o);
    if (lane == 0){
        float mx = acc[0];
#pragma unroll
        for (int e = 1; e < Ee; e++) mx = fmaxf(mx, acc[e]);
        float p[Ee]; float sum = 0.f;
#pragma unroll
        for (int e = 0; e < Ee; e++){ p[e] = expf(acc[e]-mx); sum += p[e]; }
        float inv = 1.f/sum;
#pragma unroll
        for (int e = 0; e < Ee; e++) p[e] *= inv;
        int i1 = 0; float b1 = p[0];
#pragma unroll
        for (int e = 1; e < Ee; e++) if (p[e] > b1){ b1 = p[e]; i1 = e; }
        int i2 = -1; float b2 = -1.f;
#pragma unroll
        for (int e = 0; e < Ee; e++) if (e != i1 && p[e] > b2){ b2 = p[e]; i2 = e; }
        g_idx1[t]=i1; g_idx2[t]=i2; g_gate1[t]=b1; g_gate2[t]=b2;
    }
}

// ---------- capacity ----------
__global__ void k_capacity(){
    int g = blockIdx.x, tid = threadIdx.x;
    __shared__ int s_i1[Ss], s_i2[Ss], s_p1[Ss], s_p2[Ss];
    __shared__ int s_slot[Ee*Cc];
    __shared__ int s_cnt[Ee], s_m1c[Ee];
    for (int s = tid; s < Ss; s += blockDim.x){
        s_i1[s] = g_idx1[g*Ss+s]; s_i2[s] = g_idx2[g*Ss+s];
    }
    for (int i = tid; i < Ee*Cc; i += blockDim.x) s_slot[i] = -1;
    if (tid < Ee) s_cnt[tid] = 0;
    __syncthreads();
    if (tid == 0){
        for (int s = 0; s < Ss; s++){
            int e = s_i1[s]; int p = s_cnt[e]++;
            if (p < Cc){ s_p1[s] = p; s_slot[e*Cc+p] = s; } else s_p1[s] = -1;
        }
#pragma unroll
        for (int e = 0; e < Ee; e++){ s_m1c[e] = min(s_cnt[e], Cc); s_cnt[e] = 0; }
        for (int s = 0; s < Ss; s++){
            int e = s_i2[s]; int p = s_cnt[e]++ + s_m1c[e];
            if (p < Cc){ s_p2[s] = p; s_slot[e*Cc+p] = s; } else s_p2[s] = -1;
        }
    }
    __syncthreads();
    for (int i = tid; i < Ee*Cc; i += blockDim.x){
        int e = i/Cc, c = i%Cc;
        g_slotsrc[e*GCv + g*Cc + c] = s_slot[i];
    }
    for (int s = tid; s < Ss; s += blockDim.x){
        int p1 = s_p1[s], p2 = s_p2[s], e1 = s_i1[s], e2 = s_i2[s];
        g_tokinfo[g*Ss+s] = make_int2(p1 >= 0 ? e1*GCv + g*Cc + p1 : -1,
                                      p2 >= 0 ? e2*GCv + g*Cc + p2 : -1);
    }
}

// ---------- transpose+convert body (vectorized 8B stores) ----------
__device__ __forceinline__ void splitT_body(const float* __restrict__ src,
                                            __half* __restrict__ dst,
                                            int e, int r0, int c0,
                                            int R, int C, int Cp, int Rp, int tid){
    __shared__ float t[32][33];
    int tx = tid & 31, ty = tid >> 5;
    const float* s = src + (size_t)e*R*C;
#pragma unroll
    for (int i = 0; i < 4; i++){
        int rr = r0+ty+i*8, cc = c0+tx;
        t[ty+i*8][tx] = (rr < R && cc < C) ? s[(size_t)rr*C+cc] : 0.f;
    }
    __syncthreads();
    // output: thread tid -> dr = tid>>3 (0..31), dc4 = (tid&7)*4, one 8B store.
    // dst[(c0+dr)*Rp + r0+dc4 + j] = src[r0+dc4+j][c0+dr] = t[dc4+j][dr]
    size_t dbase = (size_t)e*Cp*Rp;
    int dr  = tid >> 3;
    int dc4 = (tid & 7) * 4;
    uint32_t lo = packh(t[dc4+0][dr], t[dc4+1][dr]);
    uint32_t hi = packh(t[dc4+2][dr], t[dc4+3][dr]);
    *(uint2*)(dst + dbase + (size_t)(c0+dr)*Rp + (r0+dc4)) = make_uint2(lo, hi);
}

// ---------- fused prep ----------
#define NGATH (Ee*GCv)                          // 16384
#define NSPL  (32*172*Ee)                        // 44032
#define NSPLW (172*32*Ee)                        // 44032
__global__ void k_prep(const float* __restrict__ x,
                       const float* __restrict__ w0,
                       const float* __restrict__ w1,
                       const float* __restrict__ wo){
    int b = blockIdx.x;
    int tid = threadIdx.x;
    if (b < NGATH){
        int row = b;
        int g = (row % GCv) / Cc;
        int src = g_slotsrc[row];
        float4 v = make_float4(0.f,0.f,0.f,0.f);
        if (src >= 0) v = ((const float4*)(x + (size_t)(g*Ss+src)*Mdim))[tid];
        ((uint2*)(g_a + (size_t)row*Mdim))[tid] = make_uint2(packh(v.x,v.y), packh(v.z,v.w));
        return;
    }
    int b2 = b - NGATH;
    if (b2 < 2*NSPL){
        int which = b2 / NSPL;
        int r = b2 % NSPL;
        int bx = r % 32;
        int by = (r / 32) % 172;
        int e  = r / (32*172);
        splitT_body(which ? w1 : w0, which ? g_w1t : g_w0t,
                    e, bx*32, by*32, Mdim, Hh, Hp, Mdim, tid);
    } else {
        int r = b2 - 2*NSPL;
        int bx = r % 172;
        int by = (r / 172) % 32;
        int e  = r / (172*32);
        splitT_body(wo, g_wot, e, bx*32, by*32, Hh, Mdim, Mdim, Hp, tid);
    }
}

#define ROWB  144                    // 64 halfs (128B) + 16B pad
#define MATB  18432                  // 128 rows x 144B

// ---------- fused GEMM1 (fp16): A x {W0,W1} -> gelu*mul -> hid fp16 ----------
// 512 threads, CTA 128x128, warps 4x4 (warp 32x32), K-step 64, 3-stage pipeline.
#define STG1 (3*MATB)                // A, B0, B1 = 55296/stage
__global__ void __launch_bounds__(512, 1) k_mma1(){
    constexpr int K = Mdim;
    constexpr int NKS = K / 64;      // 16

    extern __shared__ __align__(128) char smem[];
    const uint32_t sb = s2u(smem);

    const int tid  = threadIdx.x;
    const int lane = tid & 31;
    const int wrp  = tid >> 5;
    const int wm   = (wrp >> 2) * 32;
    const int wn   = (wrp & 3) * 32;
    const int e  = blockIdx.z;
    const int bm = blockIdx.y * 128;
    const int bn = blockIdx.x * 128;

    const char* pA  = (const char*)(g_a   + ((size_t)e*GCv + bm)*K);
    const char* pB0 = (const char*)(g_w0t + ((size_t)e*Hp  + bn)*K);
    const char* pB1 = (const char*)(g_w1t + ((size_t)e*Hp  + bn)*K);

    auto load_stage = [&](int ks, int buf){
        uint32_t s = sb + buf*STG1;
        size_t ko = (size_t)ks * 128;            // 64 halfs = 128 bytes
#pragma unroll
        for (int it = 0; it < 2; it++){
            int ci = tid*2 + it;                 // 1024 chunks per matrix
            int r = ci >> 3, q = (ci & 7)*16;
            uint32_t so = (uint32_t)(r*ROWB + q);
            size_t go = (size_t)r*(K*2) + ko + q;
            cpa16(s +          so, pA  + go);
            cpa16(s + MATB   + so, pB0 + go);
            cpa16(s + 2*MATB + so, pB1 + go);
        }
        CP_COMMIT();
    };

    float d0[2][4][4], d1[2][4][4];
#pragma unroll
    for (int i = 0; i < 2; i++)
#pragma unroll
        for (int j = 0; j < 4; j++)
#pragma unroll
            for (int q = 0; q < 4; q++){ d0[i][j][q] = 0.f; d1[i][j][q] = 0.f; }

    load_stage(0, 0);
    load_stage(1, 1);

    const uint32_t brow = (uint32_t)((lane & 7) + ((lane >> 4) & 1)*8);
    const uint32_t bcol = (uint32_t)(((lane >> 3) & 1)*16);
    const uint32_t arow = (uint32_t)(lane & 15);
    const uint32_t acol = (uint32_t)((lane >> 4)*16);

    for (int ks = 0; ks < NKS; ks++){
        if (ks < NKS-1) CP_WAIT1(); else CP_WAIT0();
        __syncthreads();
        if (ks + 2 < NKS) load_stage(ks + 2, (ks + 2) % 3);

        uint32_t s0 = sb + (ks % 3)*STG1;
#pragma unroll
        for (int kk = 0; kk < 4; kk++){
            uint32_t a[2][4], b0[2][4], b1[2][4];
#pragma unroll
            for (int mt = 0; mt < 2; mt++){
                uint32_t ad = s0 + (uint32_t)(wm + mt*16)*ROWB + arow*ROWB
                                 + (uint32_t)kk*32 + acol;
                LDSM4(a[mt], ad);
            }
#pragma unroll
            for (int np = 0; np < 2; np++){
                uint32_t bd = s0 + MATB + (uint32_t)(wn + np*16)*ROWB + brow*ROWB
                                 + (uint32_t)kk*32 + bcol;
                LDSM4(b0[np], bd);
                LDSM4(b1[np], bd + MATB);
            }
#pragma unroll
            for (int mt = 0; mt < 2; mt++)
#pragma unroll
                for (int np = 0; np < 2; np++){
                    MMA_F16(d0[mt][np*2+0], a[mt], (&b0[np][0]));
                    MMA_F16(d0[mt][np*2+1], a[mt], (&b0[np][2]));
                    MMA_F16(d1[mt][np*2+0], a[mt], (&b1[np][0]));
                    MMA_F16(d1[mt][np*2+1], a[mt], (&b1[np][2]));
                }
        }
    }

    const int rb = bm + wm + (lane >> 2);
    const int cb = bn + wn + 2*(lane & 3);
#pragma unroll
    for (int mt = 0; mt < 2; mt++)
#pragma unroll
        for (int nt = 0; nt < 4; nt++)
#pragma unroll
            for (int h = 0; h < 2; h++){
                int row = rb + mt*16 + h*8;
                int col = cb + nt*8;
                float ha = gelu_f(d0[mt][nt][h*2+0]) * d1[mt][nt][h*2+0];
                float hb = gelu_f(d0[mt][nt][h*2+1]) * d1[mt][nt][h*2+1];
                size_t idx = ((size_t)e*GCv + row)*(size_t)Hp + col;
                *(uint32_t*)(g_hid + idx) = packh(ha, hb);
            }
}

// ---------- GEMM2 (fp16): hid x woT -> expout fp32 ----------
#define STG2 (2*MATB)                // A, B = 36864/stage
__global__ void __launch_bounds__(512, 1) k_mma2(){
    constexpr int K = Hp;
    constexpr int NKS = K / 64;      // 86

    extern __shared__ __align__(128) char smem[];
    const uint32_t sb = s2u(smem);

    const int tid  = threadIdx.x;
    const int lane = tid & 31;
    const int wrp  = tid >> 5;
    const int wm   = (wrp >> 2) * 32;
    const int wn   = (wrp & 3) * 32;
    const int e  = blockIdx.z;
    const int bm = blockIdx.y * 128;
    const int bn = blockIdx.x * 128;

    const char* pA = (const char*)(g_hid + ((size_t)e*GCv  + bm)*K);
    const char* pB = (const char*)(g_wot + ((size_t)e*Mdim + bn)*K);

    auto load_stage = [&](int ks, int buf){
        uint32_t s = sb + buf*STG2;
        size_t ko = (size_t)ks * 128;
#pragma unroll
        for (int it = 0; it < 2; it++){
            int ci = tid*2 + it;
            int r = ci >> 3, q = (ci & 7)*16;
            uint32_t so = (uint32_t)(r*ROWB + q);
            size_t go = (size_t)r*(K*2) + ko + q;
            cpa16(s +        so, pA + go);
            cpa16(s + MATB + so, pB + go);
        }
        CP_COMMIT();
    };

    float d[2][4][4];
#pragma unroll
    for (int i = 0; i < 2; i++)
#pragma unroll
        for (int j = 0; j < 4; j++)
#pragma unroll
            for (int q = 0; q < 4; q++) d[i][j][q] = 0.f;

    load_stage(0, 0);
    load_stage(1, 1);

    const uint32_t brow = (uint32_t)((lane & 7) + ((lane >> 4) & 1)*8);
    const uint32_t bcol = (uint32_t)(((lane >> 3) & 1)*16);
    const uint32_t arow = (uint32_t)(lane & 15);
    const uint32_t acol = (uint32_t)((lane >> 4)*16);

    for (int ks = 0; ks < NKS; ks++){
        if (ks < NKS-1) CP_WAIT1(); else CP_WAIT0();
        __syncthreads();
        if (ks + 2 < NKS) load_stage(ks + 2, (ks + 2) % 3);

        uint32_t s0 = sb + (ks % 3)*STG2;
#pragma unroll
        for (int kk = 0; kk < 4; kk++){
            uint32_t a[2][4], b[2][4];
#pragma unroll
            for (int mt = 0; mt < 2; mt++){
                uint32_t ad = s0 + (uint32_t)(wm + mt*16)*ROWB + arow*ROWB
                                 + (uint32_t)kk*32 + acol;
                LDSM4(a[mt], ad);
            }
#pragma unroll
            for (int np = 0; np < 2; np++){
                uint32_t bd = s0 + MATB + (uint32_t)(wn + np*16)*ROWB + brow*ROWB
                                 + (uint32_t)kk*32 + bcol;
                LDSM4(b[np], bd);
            }
#pragma unroll
            for (int mt = 0; mt < 2; mt++)
#pragma unroll
                for (int np = 0; np < 2; np++){
                    MMA_F16(d[mt][np*2+0], a[mt], (&b[np][0]));
                    MMA_F16(d[mt][np*2+1], a[mt], (&b[np][2]));
                }
        }
    }

    const int rb = bm + wm + (lane >> 2);
    const int cb = bn + wn + 2*(lane & 3);
#pragma unroll
    for (int mt = 0; mt < 2; mt++)
#pragma unroll
        for (int nt = 0; nt < 4; nt++)
#pragma unroll
            for (int h = 0; h < 2; h++){
                int row = rb + mt*16 + h*8;
                int col = cb + nt*8;
                size_t idx = ((size_t)e*GCv + row)*(size_t)Mdim + col;
                *(float2*)(g_expout + idx) = make_float2(d[mt][nt][h*2+0], d[mt][nt][h*2+1]);
            }
}

// ---------- combine ----------
__global__ void k_combine(float* __restrict__ out){
    int t = blockIdx.x, i = threadIdx.x;
    int2 info = g_tokinfo[t];
    float4 acc = make_float4(0.f,0.f,0.f,0.f);
    if (info.x >= 0){
        float gv = g_gate1[t];
        float4 v = ((const float4*)(g_expout + (size_t)info.x*Mdim))[i];
        acc.x += gv*v.x; acc.y += gv*v.y; acc.z += gv*v.z; acc.w += gv*v.w;
    }
    if (info.y >= 0){
        float gv = g_gate2[t];
        float4 v = ((const float4*)(g_expout + (size_t)info.y*Mdim))[i];
        acc.x += gv*v.x; acc.y += gv*v.y; acc.z += gv*v.z; acc.w += gv*v.w;
    }
    ((float4*)(out + (size_t)t*Mdim))[i] = acc;
}

// ---------- launch ----------
extern "C" void kernel_launch(void* const* d_in, const int* in_sizes, int n_in,
                              void* d_out, int out_size){
    const float* x  = (const float*)d_in[0];
    const float* rw = (const float*)d_in[1];
    const float* w0 = (const float*)d_in[2];
    const float* w1 = (const float*)d_in[3];
    const float* wo = (const float*)d_in[4];
    float* out = (float*)d_out;

    static bool attr_done = false;
    if (!attr_done){
        cudaFuncSetAttribute(k_mma1, cudaFuncAttributeMaxDynamicSharedMemorySize, 3*STG1);
        cudaFuncSetAttribute(k_mma2, cudaFuncAttributeMaxDynamicSharedMemorySize, 3*STG2);
        attr_done = true;
    }

    // k_mma1 is the 4th launch (the one ncu captures)
    k_router<<<Ntok/8, 256>>>(x, rw);                                    // 1
    k_capacity<<<Gg, 256>>>();                                           // 2
    k_prep<<<NGATH + 2*NSPL + NSPLW, 256>>>(x, w0, w1, wo);              // 3
    k_mma1<<<dim3(Hp/128,  GCv/128, Ee), 512, 3*STG1>>>();               // 4 <- profiled
    k_mma2<<<dim3(Mdim/128, GCv/128, Ee), 512, 3*STG2>>>();              // 5
    k_combine<<<Ntok, 256>>>(out);                                       // 6
}